// round 4
// baseline (speedup 1.0000x reference)
#include <cuda_runtime.h>
#include <math.h>

#define Bc 8
#define Dm 384
#define Hh 6
#define HD 64
#define Lc 12
#define MLPD 1536
#define NCLSD 1000
#define TMAX 577
#define NPATCH 576
#define GG 24
#define SP 640   // padded row pitch for attention matrix
#define MTOT (Bc * TMAX)   // 4616 flattened rows

// ---------------- packed fp32x2 helpers (sm_103a FFMA2 path) ----------------
__device__ __forceinline__ void ffma2(unsigned long long &acc, unsigned long long a, unsigned long long b) {
    asm("fma.rn.f32x2 %0, %1, %2, %0;" : "+l"(acc) : "l"(a), "l"(b));
}
__device__ __forceinline__ unsigned long long dup2(float v) {
    unsigned long long r;
    asm("mov.b64 %0, {%1, %1};" : "=l"(r) : "f"(v));
    return r;
}
__device__ __forceinline__ float2 u2f(unsigned long long v) {
    float2 f;
    asm("mov.b64 {%0, %1}, %2;" : "=f"(f.x), "=f"(f.y) : "l"(v));
    return f;
}

// ---------------- scratch (device globals; no allocation allowed) ----------------
__device__ float g_patches[Bc * NPATCH * 768];
__device__ float g_xA[Bc * TMAX * Dm];
__device__ float g_xB[Bc * TMAX * Dm];
__device__ float g_xn[Bc * TMAX * Dm];
__device__ float g_qkv[Bc * TMAX * 3 * Dm];
__device__ float g_S[(size_t)Bc * Hh * TMAX * SP];   // pitched attention matrix
__device__ float g_ao[Bc * TMAX * Dm];
__device__ float g_hid[Bc * TMAX * MLPD];
__device__ float g_rho_bh[Bc * Hh];
__device__ float g_raw[Bc * NPATCH];
__device__ float g_prevmass[Bc];
__device__ int   g_keep[TMAX];
__device__ int   g_Ntok;
__device__ int   g_hasprev;

// ---------------- init ----------------
__global__ void k_init() { g_Ntok = TMAX; g_hasprev = 0; }

// ---------------- patchify ----------------
__global__ void k_patchify(const float* __restrict__ x) {
    int p = blockIdx.x, b = blockIdx.y;
    int gy = p / GG, gx = p % GG;
    for (int f = threadIdx.x; f < 768; f += blockDim.x) {
        int c = f >> 8, r = (f >> 4) & 15, cc = f & 15;
        g_patches[((size_t)(b * NPATCH + p)) * 768 + f] =
            x[(((size_t)(b * 3 + c)) * 384 + gy * 16 + r) * 384 + gx * 16 + cc];
    }
}

// ---------------- 64x64x8 fp32 GEMM (FFMA2 inner), batch-flattened M ----------------
// A: [Mtotal][K] (row-major), W: [K][N], C/res: [Mtotal][N]. N%64==0, K%8==0.
__global__ void __launch_bounds__(256) k_gemm(
    const float* __restrict__ A, int Mtotal, int K,
    const float* __restrict__ W, int N,
    const float* __restrict__ bias,
    const float* __restrict__ res,
    float* __restrict__ C,
    int act, int useDyn)
{
    int m0 = blockIdx.y * 64;
    int n0 = blockIdx.x * 64;
    if (useDyn) {
        int ntok = g_Ntok;
        int tstart = m0 % TMAX;
        if (tstart >= ntok && tstart + 63 < TMAX) return;   // fully dead tile
    }
    __shared__ __align__(16) float As[8][64];
    __shared__ __align__(16) float Bsd[8][192];   // duplicated B: 16 groups x 12 floats (8 used)
    int tid = threadIdx.x;
    int tx = tid & 15, ty = tid >> 4;

    bool isA = (tid < 128);
    int arow = (tid & 127) >> 1;
    int acol = (tid & 1) * 4;
    int brow = (tid & 127) >> 4;
    int bgrp = (tid & 15);
    int am = m0 + arow;
    bool aval = isA && (am < Mtotal);
    const float* aptr = A + (size_t)(aval ? am : 0) * K + acol;
    const float* bptr = W + (size_t)brow * N + n0 + bgrp * 4;

    float4 pre;
    if (isA) pre = aval ? *(const float4*)aptr : make_float4(0.f, 0.f, 0.f, 0.f);
    else     pre = *(const float4*)bptr;

    unsigned long long acc01[4] = {0ull, 0ull, 0ull, 0ull};
    unsigned long long acc23[4] = {0ull, 0ull, 0ull, 0ull};

    for (int k0 = 0; k0 < K; k0 += 8) {
        if (isA) {
            As[acol + 0][arow] = pre.x; As[acol + 1][arow] = pre.y;
            As[acol + 2][arow] = pre.z; As[acol + 3][arow] = pre.w;
        } else {
            float* dp = &Bsd[brow][bgrp * 12];
            *(float4*)dp       = make_float4(pre.x, pre.x, pre.y, pre.y);
            *(float4*)(dp + 4) = make_float4(pre.z, pre.z, pre.w, pre.w);
        }
        __syncthreads();
        if (k0 + 8 < K) {
            if (isA) pre = aval ? *(const float4*)(aptr + k0 + 8) : make_float4(0.f, 0.f, 0.f, 0.f);
            else     pre = *(const float4*)(bptr + (size_t)(k0 + 8) * N);
        }
        #pragma unroll
        for (int kk = 0; kk < 8; kk++) {
            double2 a = *(const double2*)&As[kk][ty * 4];
            unsigned long long a01 = __double_as_longlong(a.x);   // (row ty*4, row ty*4+1)
            unsigned long long a23 = __double_as_longlong(a.y);   // (row ty*4+2, row ty*4+3)
            const double2* bp = (const double2*)&Bsd[kk][tx * 12];
            double2 bA = bp[0], bB = bp[1];
            unsigned long long b0 = __double_as_longlong(bA.x);
            unsigned long long b1 = __double_as_longlong(bA.y);
            unsigned long long b2 = __double_as_longlong(bB.x);
            unsigned long long b3 = __double_as_longlong(bB.y);
            ffma2(acc01[0], a01, b0); ffma2(acc01[1], a01, b1);
            ffma2(acc01[2], a01, b2); ffma2(acc01[3], a01, b3);
            ffma2(acc23[0], a23, b0); ffma2(acc23[1], a23, b1);
            ffma2(acc23[2], a23, b2); ffma2(acc23[3], a23, b3);
        }
        __syncthreads();
    }

    float accf[4][4];
    #pragma unroll
    for (int j = 0; j < 4; j++) {
        float2 f01 = u2f(acc01[j]);
        float2 f23 = u2f(acc23[j]);
        accf[0][j] = f01.x; accf[1][j] = f01.y;
        accf[2][j] = f23.x; accf[3][j] = f23.y;
    }

    #pragma unroll
    for (int i = 0; i < 4; i++) {
        int m = m0 + ty * 4 + i;
        if (m >= Mtotal) continue;
        float* Crow = C + (size_t)m * N;
        const float* Rrow = res ? res + (size_t)m * N : (const float*)0;
        #pragma unroll
        for (int j = 0; j < 4; j++) {
            int n = n0 + tx * 4 + j;
            float v = accf[i][j] + bias[n];
            if (act == 1) v = 0.5f * v * (1.f + erff(v * 0.70710678118654752f));
            if (Rrow) v += Rrow[n];
            Crow[n] = v;
        }
    }
}

// ---------------- embed ----------------
__global__ void k_embed(const float* __restrict__ cls, const float* __restrict__ pos,
                        const float* __restrict__ tok, float* __restrict__ X) {
    int t = blockIdx.x, b = blockIdx.y, d = threadIdx.x;
    const float4* src = (t == 0) ? (const float4*)cls
                                 : (const float4*)&tok[((size_t)(b * NPATCH + t - 1)) * Dm];
    float4 v = src[d];
    float4 p = ((const float4*)&pos[(size_t)t * Dm])[d];
    v.x += p.x; v.y += p.y; v.z += p.z; v.w += p.w;
    ((float4*)&X[((size_t)(b * TMAX + t)) * Dm])[d] = v;
}

// ---------------- LayerNorm ----------------
__global__ void k_ln(const float* __restrict__ X, const float* __restrict__ s,
                     const float* __restrict__ bb, float* __restrict__ O,
                     int useDyn, int ntokFixed) {
    int ntok = useDyn ? g_Ntok : ntokFixed;
    int t = blockIdx.x; if (t >= ntok) return;
    int b = blockIdx.y;
    const float* xr = X + ((size_t)(b * TMAX + t)) * Dm;
    __shared__ float red[128];
    int tid = threadIdx.x;
    float v0 = xr[tid], v1 = xr[tid + 128], v2 = xr[tid + 256];
    red[tid] = v0 + v1 + v2; __syncthreads();
    for (int st = 64; st > 0; st >>= 1) { if (tid < st) red[tid] += red[tid + st]; __syncthreads(); }
    float mean = red[0] / 384.f; __syncthreads();
    float d0 = v0 - mean, d1 = v1 - mean, d2 = v2 - mean;
    red[tid] = d0 * d0 + d1 * d1 + d2 * d2; __syncthreads();
    for (int st = 64; st > 0; st >>= 1) { if (tid < st) red[tid] += red[tid + st]; __syncthreads(); }
    float var = red[0] / 384.f;
    float inv = 1.f / sqrtf(var + 1e-5f);
    float* orow = O + ((size_t)(b * TMAX + t)) * Dm;
    orow[tid]       = d0 * inv * s[tid]       + bb[tid];
    orow[tid + 128] = d1 * inv * s[tid + 128] + bb[tid + 128];
    orow[tid + 256] = d2 * inv * s[tid + 256] + bb[tid + 256];
}

// ---------------- attention scores S = Q K^T * hd^-0.5 (64x64 tiles) ----------------
__global__ void __launch_bounds__(256) k_qk(const float* __restrict__ qkv) {
    int ntok = g_Ntok;
    int b = blockIdx.z / Hh, h = blockIdx.z % Hh;
    int q0 = blockIdx.y * 64, k0 = blockIdx.x * 64;
    if (q0 >= ntok || k0 >= ntok) return;
    __shared__ float Qs[64][65];
    __shared__ float Ks[64][65];
    int tid = threadIdx.x;
    #pragma unroll
    for (int i = 0; i < 4; i++) {
        int idx = tid + i * 256;
        int r = idx >> 4, d4 = (idx & 15) * 4;
        int tq = q0 + r, tk = k0 + r;
        float4 qv = (tq < ntok) ? *(const float4*)&qkv[((size_t)(b * TMAX + tq)) * 1152 + h * 64 + d4]
                                : make_float4(0.f, 0.f, 0.f, 0.f);
        float4 kv = (tk < ntok) ? *(const float4*)&qkv[((size_t)(b * TMAX + tk)) * 1152 + 384 + h * 64 + d4]
                                : make_float4(0.f, 0.f, 0.f, 0.f);
        Qs[r][d4] = qv.x; Qs[r][d4 + 1] = qv.y; Qs[r][d4 + 2] = qv.z; Qs[r][d4 + 3] = qv.w;
        Ks[r][d4] = kv.x; Ks[r][d4 + 1] = kv.y; Ks[r][d4 + 2] = kv.z; Ks[r][d4 + 3] = kv.w;
    }
    __syncthreads();
    int tx = tid & 15, ty = tid >> 4;
    float acc[4][4] = {};
    #pragma unroll 8
    for (int d = 0; d < 64; d++) {
        float a0 = Qs[ty * 4 + 0][d], a1 = Qs[ty * 4 + 1][d];
        float a2 = Qs[ty * 4 + 2][d], a3 = Qs[ty * 4 + 3][d];
        float b0 = Ks[tx * 4 + 0][d], b1 = Ks[tx * 4 + 1][d];
        float b2 = Ks[tx * 4 + 2][d], b3 = Ks[tx * 4 + 3][d];
        acc[0][0] += a0 * b0; acc[0][1] += a0 * b1; acc[0][2] += a0 * b2; acc[0][3] += a0 * b3;
        acc[1][0] += a1 * b0; acc[1][1] += a1 * b1; acc[1][2] += a1 * b2; acc[1][3] += a1 * b3;
        acc[2][0] += a2 * b0; acc[2][1] += a2 * b1; acc[2][2] += a2 * b2; acc[2][3] += a2 * b3;
        acc[3][0] += a3 * b0; acc[3][1] += a3 * b1; acc[3][2] += a3 * b2; acc[3][3] += a3 * b3;
    }
    float* Sb = g_S + ((size_t)(b * Hh + h)) * TMAX * SP;
    #pragma unroll
    for (int i = 0; i < 4; i++) {
        int q = q0 + ty * 4 + i;
        if (q >= ntok) continue;
        #pragma unroll
        for (int j = 0; j < 4; j++) {
            int k = k0 + tx * 4 + j;
            if (k < ntok) Sb[(size_t)q * SP + k] = acc[i][j] * 0.125f;
        }
    }
}

// ---------------- softmax rows (in place, pitched) + CLS entropy fused ----------------
__global__ void k_softmax() {
    int ntok = g_Ntok;
    int q = blockIdx.x; if (q >= ntok) return;
    int bh = blockIdx.y;
    float* row = g_S + ((size_t)bh * TMAX + q) * SP;
    __shared__ float red[256];
    int tid = threadIdx.x;
    float v[3]; float mx = -1e30f;
    #pragma unroll
    for (int i = 0; i < 3; i++) {
        int k = tid + 256 * i;
        v[i] = (k < ntok) ? row[k] : -1e30f;
        mx = fmaxf(mx, v[i]);
    }
    red[tid] = mx; __syncthreads();
    for (int st = 128; st > 0; st >>= 1) { if (tid < st) red[tid] = fmaxf(red[tid], red[tid + st]); __syncthreads(); }
    mx = red[0]; __syncthreads();
    float sm = 0.f;
    #pragma unroll
    for (int i = 0; i < 3; i++) {
        int k = tid + 256 * i;
        v[i] = (k < ntok) ? expf(v[i] - mx) : 0.f;
        sm += v[i];
    }
    red[tid] = sm; __syncthreads();
    for (int st = 128; st > 0; st >>= 1) { if (tid < st) red[tid] += red[tid + st]; __syncthreads(); }
    float inv = 1.f / red[0];
    #pragma unroll
    for (int i = 0; i < 3; i++) {
        int k = tid + 256 * i;
        if (k < ntok) row[k] = v[i] * inv;
    }
    if (q == 0) {
        __syncthreads();
        float e = 0.f;
        #pragma unroll
        for (int i = 0; i < 3; i++) {
            int k = tid + 256 * i;
            if (k < ntok) { float p = v[i] * inv; e += p * logf(p + 1e-6f); }
        }
        red[tid] = e; __syncthreads();
        for (int st = 128; st > 0; st >>= 1) { if (tid < st) red[tid] += red[tid + st]; __syncthreads(); }
        if (tid == 0) g_rho_bh[bh] = -red[0] / logf((float)ntok);
    }
}

// ---------------- out = attn @ V (FFMA2 inner) ----------------
__global__ void __launch_bounds__(256) k_av(const float* __restrict__ qkv) {
    int ntok = g_Ntok;
    int q0 = blockIdx.x * 64; if (q0 >= ntok) return;
    int h = blockIdx.y, b = blockIdx.z;
    __shared__ float Ps[64][65];
    __shared__ __align__(16) float Vs[64][68];
    int tid = threadIdx.x, tx = tid & 15, ty = tid >> 4;
    unsigned long long accA[4] = {0ull, 0ull, 0ull, 0ull};   // cols (tx*4, tx*4+1)
    unsigned long long accB[4] = {0ull, 0ull, 0ull, 0ull};   // cols (tx*4+2, tx*4+3)
    const float* Sb = g_S + ((size_t)(b * Hh + h)) * TMAX * SP;
    for (int k0 = 0; k0 < ntok; k0 += 64) {
        #pragma unroll
        for (int i = 0; i < 4; i++) {
            int idx = tid + i * 256;
            int r = idx >> 4, c4 = (idx & 15) * 4;
            int q = q0 + r;
            float4 pv = (q < ntok) ? *(const float4*)&Sb[(size_t)q * SP + k0 + c4]
                                   : make_float4(0.f, 0.f, 0.f, 0.f);
            Ps[r][c4] = pv.x; Ps[r][c4 + 1] = pv.y; Ps[r][c4 + 2] = pv.z; Ps[r][c4 + 3] = pv.w;
            int k = k0 + r;
            float4 vv = (k < ntok) ? *(const float4*)&qkv[((size_t)(b * TMAX + k)) * 1152 + 768 + h * 64 + c4]
                                   : make_float4(0.f, 0.f, 0.f, 0.f);
            Vs[r][c4] = vv.x; Vs[r][c4 + 1] = vv.y; Vs[r][c4 + 2] = vv.z; Vs[r][c4 + 3] = vv.w;
        }
        __syncthreads();
        #pragma unroll 8
        for (int kk = 0; kk < 64; kk++) {
            unsigned long long d0 = dup2(Ps[ty * 4 + 0][kk]);
            unsigned long long d1 = dup2(Ps[ty * 4 + 1][kk]);
            unsigned long long d2 = dup2(Ps[ty * 4 + 2][kk]);
            unsigned long long d3 = dup2(Ps[ty * 4 + 3][kk]);
            double2 bv = *(const double2*)&Vs[kk][tx * 4];
            unsigned long long b01 = __double_as_longlong(bv.x);
            unsigned long long b23 = __double_as_longlong(bv.y);
            ffma2(accA[0], d0, b01); ffma2(accB[0], d0, b23);
            ffma2(accA[1], d1, b01); ffma2(accB[1], d1, b23);
            ffma2(accA[2], d2, b01); ffma2(accB[2], d2, b23);
            ffma2(accA[3], d3, b01); ffma2(accB[3], d3, b23);
        }
        __syncthreads();
    }
    #pragma unroll
    for (int i = 0; i < 4; i++) {
        int q = q0 + ty * 4 + i;
        if (q >= ntok) continue;
        float2 fA = u2f(accA[i]);
        float2 fB = u2f(accB[i]);
        float* orow = &g_ao[((size_t)(b * TMAX + q)) * Dm + h * 64 + tx * 4];
        orow[0] = fA.x; orow[1] = fA.y; orow[2] = fB.x; orow[3] = fB.y;
    }
}

// ---------------- stats: raw[b,k] = sum_h attn[b,h,0,k+1] * ||v[b,h,k+1]|| ----------------
__global__ void k_stats(const float* __restrict__ qkv) {
    int ntok = g_Ntok;
    int k = blockIdx.x * 192 + threadIdx.x;
    int b = blockIdx.y;
    if (k >= ntok - 1) return;
    const float4* vb = (const float4*)&qkv[((size_t)(b * TMAX + k + 1)) * 1152 + 768];
    const float* S0 = g_S + ((size_t)(b * Hh)) * TMAX * SP + (k + 1);
    float racc = 0.f;
    #pragma unroll
    for (int h = 0; h < Hh; h++) {
        float ss = 0.f;
        #pragma unroll
        for (int i = 0; i < 16; i++) {
            float4 v = vb[h * 16 + i];
            ss += v.x * v.x + v.y * v.y + v.z * v.z + v.w * v.w;
        }
        racc += S0[(size_t)h * TMAX * SP] * sqrtf(ss);
    }
    g_raw[b * NPATCH + k] = racc;
}

// ---------------- prune: mass + scores + controller + top-k + keep list ----------------
__global__ void k_prune() {
    __shared__ float sMass[Bc];
    __shared__ float wsum[Bc][18];
    __shared__ float sc[NPATCH];
    __shared__ unsigned char kp[NPATCH];
    __shared__ int sNn;
    int ntok = g_Ntok, Np = ntok - 1;
    int tid = threadIdx.x;
    int wid = tid >> 5, lid = tid & 31;

    #pragma unroll
    for (int b = 0; b < Bc; b++) {
        float v = (tid < Np) ? g_raw[b * NPATCH + tid] : 0.f;
        #pragma unroll
        for (int o = 16; o > 0; o >>= 1) v += __shfl_down_sync(0xffffffffu, v, o);
        if (lid == 0) wsum[b][wid] = v;
    }
    __syncthreads();
    if (tid < Bc) {
        float m = 0.f;
        for (int w = 0; w < 18; w++) m += wsum[tid][w];
        sMass[tid] = m;
    }
    __syncthreads();

    float score = 0.f;
    if (tid < Np) {
        #pragma unroll
        for (int b = 0; b < Bc; b++) score += g_raw[b * NPATCH + tid] / (sMass[b] + 1e-6f);
        score *= 0.125f;
    }
    sc[tid] = score;

    if (tid == 0) {
        int nn;
        if (Np > 16) {
            float mr = 0.f;
            for (int i = 0; i < Bc * Hh; i++) mr += g_rho_bh[i];
            mr /= 48.f;
            if (g_hasprev) {
                float md = 0.f;
                for (int b = 0; b < Bc; b++)
                    md += fabsf(sMass[b] - g_prevmass[b]) / (g_prevmass[b] + 1e-6f);
                md /= 8.f;
                float kr = 1.0f - 0.1f * (mr + md);
                kr = fminf(fmaxf(kr, 0.f), 1.f);
                nn = (int)((double)Np * (double)kr);
                if (nn < 16) nn = 16;
            } else {
                nn = Np;
            }
            for (int b = 0; b < Bc; b++) g_prevmass[b] = sMass[b];
            g_hasprev = 1;
        } else {
            nn = Np;
        }
        sNn = nn;
    }
    __syncthreads();
    int nn = sNn;

    int keep = 0;
    if (tid < Np) {
        float s = sc[tid];
        int rank = 0;
        for (int j = 0; j < Np; j++) {
            float o = sc[j];
            rank += (o > s) || (o == s && j < tid);
        }
        keep = (rank < nn);
    }
    kp[tid] = (unsigned char)keep;
    __syncthreads();
    if (keep) {
        int pos = 0;
        for (int j = 0; j < tid; j++) pos += kp[j];
        g_keep[pos + 1] = tid + 1;
    }
    if (tid == 0) { g_keep[0] = 0; g_Ntok = nn + 1; }
}

// ---------------- gather ----------------
__global__ void k_gather(const float* __restrict__ src, float* __restrict__ dst) {
    int ntok = g_Ntok;
    int t = blockIdx.x; if (t >= ntok) return;
    int b = blockIdx.y, d = threadIdx.x;
    int st = g_keep[t];
    ((float4*)&dst[((size_t)(b * TMAX + t)) * Dm])[d] =
        ((const float4*)&src[((size_t)(b * TMAX + st)) * Dm])[d];
}

// ---------------- classification head ----------------
__global__ void k_head(const float* __restrict__ xn, const float* __restrict__ W,
                       const float* __restrict__ bb, float* __restrict__ out) {
    int n = blockIdx.x * 128 + threadIdx.x;
    int b = blockIdx.y;
    if (n >= NCLSD) return;
    const float* xr = xn + (size_t)b * TMAX * Dm;
    float s = 0.f;
    for (int k = 0; k < Dm; k++) s += xr[k] * W[(size_t)k * NCLSD + n];
    out[b * NCLSD + n] = s + bb[n];
}

// ================================= host =================================
extern "C" void kernel_launch(void* const* d_in, const int* in_sizes, int n_in,
                              void* d_out, int out_size) {
    const float* x       = (const float*)d_in[0];
    const float* patch_w = (const float*)d_in[1];
    const float* patch_b = (const float*)d_in[2];
    const float* cls     = (const float*)d_in[3];
    const float* pos     = (const float*)d_in[4];
    const float* ln1_s   = (const float*)d_in[5];
    const float* ln1_b   = (const float*)d_in[6];
    const float* qkv_w   = (const float*)d_in[7];
    const float* qkv_b   = (const float*)d_in[8];
    const float* proj_w  = (const float*)d_in[9];
    const float* proj_b  = (const float*)d_in[10];
    const float* ln2_s   = (const float*)d_in[11];
    const float* ln2_b   = (const float*)d_in[12];
    const float* fc1_w   = (const float*)d_in[13];
    const float* fc1_b   = (const float*)d_in[14];
    const float* fc2_w   = (const float*)d_in[15];
    const float* fc2_b   = (const float*)d_in[16];
    const float* norm_s  = (const float*)d_in[17];
    const float* norm_b  = (const float*)d_in[18];
    const float* head_w  = (const float*)d_in[19];
    const float* head_b  = (const float*)d_in[20];
    float* out = (float*)d_out;

    float *pPatches, *pXA, *pXB, *pXn, *pQkv, *pAo, *pHid;
    cudaGetSymbolAddress((void**)&pPatches, g_patches);
    cudaGetSymbolAddress((void**)&pXA,  g_xA);
    cudaGetSymbolAddress((void**)&pXB,  g_xB);
    cudaGetSymbolAddress((void**)&pXn,  g_xn);
    cudaGetSymbolAddress((void**)&pQkv, g_qkv);
    cudaGetSymbolAddress((void**)&pAo,  g_ao);
    cudaGetSymbolAddress((void**)&pHid, g_hid);

    const int mT  = (MTOT + 63) / 64;            // 73 flattened M-tiles
    const int mTp = (Bc * NPATCH + 63) / 64;     // 72 for patch embed

    k_init<<<1, 1>>>();
    k_patchify<<<dim3(NPATCH, Bc), 256>>>(x);
    k_gemm<<<dim3(Dm / 64, mTp), 256>>>(
        pPatches, Bc * NPATCH, 768, patch_w, Dm, patch_b, (const float*)0, pAo, 0, 0);
    k_embed<<<dim3(TMAX, Bc), 96>>>(cls, pos, pAo, pXA);

    float* src = pXA;
    float* dst = pXB;
    const int aTiles = (TMAX + 63) / 64;     // 10
    for (int l = 0; l < Lc; l++) {
        k_ln<<<dim3(TMAX, Bc), 128>>>(src, ln1_s + l * Dm, ln1_b + l * Dm, pXn, 1, 0);
        k_gemm<<<dim3(1152 / 64, mT), 256>>>(
            pXn, MTOT, Dm, qkv_w + (size_t)l * Dm * 1152, 1152, qkv_b + l * 1152,
            (const float*)0, pQkv, 0, 1);
        k_qk<<<dim3(aTiles, aTiles, Bc * Hh), 256>>>(pQkv);
        k_softmax<<<dim3(TMAX, Bc * Hh), 256>>>();
        k_av<<<dim3(aTiles, Hh, Bc), 256>>>(pQkv);
        k_stats<<<dim3(3, Bc), 192>>>(pQkv);
        k_gemm<<<dim3(Dm / 64, mT), 256>>>(
            pAo, MTOT, Dm, proj_w + (size_t)l * Dm * Dm, Dm, proj_b + l * Dm,
            src, src, 0, 1);
        k_ln<<<dim3(TMAX, Bc), 128>>>(src, ln2_s + l * Dm, ln2_b + l * Dm, pXn, 1, 0);
        k_gemm<<<dim3(MLPD / 64, mT), 256>>>(
            pXn, MTOT, Dm, fc1_w + (size_t)l * Dm * MLPD, MLPD, fc1_b + l * MLPD,
            (const float*)0, pHid, 1, 1);
        k_gemm<<<dim3(Dm / 64, mT), 256>>>(
            pHid, MTOT, MLPD, fc2_w + (size_t)l * MLPD * Dm, Dm, fc2_b + l * Dm,
            src, src, 0, 1);
        k_prune<<<1, NPATCH>>>();
        k_gather<<<dim3(TMAX, Bc), 96>>>(src, dst);
        float* tmp = src; src = dst; dst = tmp;
    }

    k_ln<<<dim3(1, Bc), 128>>>(src, norm_s, norm_b, pXn, 0, 1);
    k_head<<<dim3((NCLSD + 127) / 128, Bc), 128>>>(pXn, head_w, head_b, out);
}

// round 5
// speedup vs baseline: 1.3268x; 1.3268x over previous
#include <cuda_runtime.h>
#include <math.h>

#define Bc 8
#define Dm 384
#define Hh 6
#define HD 64
#define Lc 12
#define MLPD 1536
#define NCLSD 1000
#define TMAX 577
#define NPATCH 576
#define GG 24
#define SP 640   // padded row pitch for attention matrix
#define MTOT (Bc * TMAX)   // 4616 flattened rows

#define BM 128
#define BN 64
#define BK 16
#define APAD 132
#define BPAD 68

// ---------------- scratch (device globals; no allocation allowed) ----------------
__device__ float g_patches[Bc * NPATCH * 768];
__device__ float g_xA[Bc * TMAX * Dm];
__device__ float g_xB[Bc * TMAX * Dm];
__device__ float g_xn[Bc * TMAX * Dm];
__device__ float g_qkv[Bc * TMAX * 3 * Dm];
__device__ float g_S[(size_t)Bc * Hh * TMAX * SP];   // pitched attention matrix
__device__ float g_ao[Bc * TMAX * Dm];
__device__ float g_hid[Bc * TMAX * MLPD];
__device__ float g_rho_bh[Bc * Hh];
__device__ float g_raw[Bc * NPATCH];
__device__ float g_prevmass[Bc];
__device__ int   g_keep[TMAX];
__device__ int   g_Ntok;
__device__ int   g_hasprev;

// ---------------- init ----------------
__global__ void k_init() { g_Ntok = TMAX; g_hasprev = 0; }

// ---------------- patchify ----------------
__global__ void k_patchify(const float* __restrict__ x) {
    int p = blockIdx.x, b = blockIdx.y;
    int gy = p / GG, gx = p % GG;
    for (int f = threadIdx.x; f < 768; f += blockDim.x) {
        int c = f >> 8, r = (f >> 4) & 15, cc = f & 15;
        g_patches[((size_t)(b * NPATCH + p)) * 768 + f] =
            x[(((size_t)(b * 3 + c)) * 384 + gy * 16 + r) * 384 + gx * 16 + cc];
    }
}

// ---------------- 128x64x16 fp32 GEMM, double-buffered, batch-flattened M ----------------
// A: [Mtotal][K] (row-major), W: [K][N], C/res: [Mtotal][N]. N%64==0, K%16==0.
__global__ void __launch_bounds__(256) k_gemm(
    const float* __restrict__ A, int Mtotal, int K,
    const float* __restrict__ W, int N,
    const float* __restrict__ bias,
    const float* __restrict__ res,
    float* __restrict__ C,
    int act, int useDyn)
{
    int m0 = blockIdx.y * BM;
    int n0 = blockIdx.x * BN;
    if (useDyn) {
        int ntok = g_Ntok;
        int tstart = m0 % TMAX;
        if (tstart >= ntok && tstart + BM - 1 < TMAX) return;   // fully dead tile
    }
    __shared__ __align__(16) float As[2][BK][APAD];
    __shared__ __align__(16) float Bs[2][BK][BPAD];

    int tid = threadIdx.x;
    int tx = tid & 15, ty = tid >> 4;

    // A load mapping: 512 float4 (128 rows x 16 k), 2 per thread
    int am_[2], ak_[2];
    bool aval[2];
    const float* aptr[2];
    #pragma unroll
    for (int i = 0; i < 2; i++) {
        int idx = tid + i * 256;
        am_[i] = idx >> 2;
        ak_[i] = (idx & 3) * 4;
        int m = m0 + am_[i];
        aval[i] = (m < Mtotal);
        aptr[i] = A + (size_t)(aval[i] ? m : 0) * K + ak_[i];
    }
    // B load mapping: 256 float4 (16 k x 64 n), 1 per thread
    int bk_ = tid >> 4;
    int bn_ = (tid & 15) * 4;
    const float* bptr = W + (size_t)bk_ * N + n0 + bn_;

    // prologue: fetch tile 0
    float4 avr[2], bvr;
    #pragma unroll
    for (int i = 0; i < 2; i++)
        avr[i] = aval[i] ? *(const float4*)(aptr[i]) : make_float4(0.f, 0.f, 0.f, 0.f);
    bvr = *(const float4*)(bptr);

    #pragma unroll
    for (int i = 0; i < 2; i++) {
        As[0][ak_[i] + 0][am_[i]] = avr[i].x;
        As[0][ak_[i] + 1][am_[i]] = avr[i].y;
        As[0][ak_[i] + 2][am_[i]] = avr[i].z;
        As[0][ak_[i] + 3][am_[i]] = avr[i].w;
    }
    *(float4*)&Bs[0][bk_][bn_] = bvr;
    __syncthreads();

    float acc[8][4] = {};
    int buf = 0;
    for (int k0 = 0; k0 < K; k0 += BK) {
        bool more = (k0 + BK < K);
        if (more) {
            #pragma unroll
            for (int i = 0; i < 2; i++)
                avr[i] = aval[i] ? *(const float4*)(aptr[i] + k0 + BK) : make_float4(0.f, 0.f, 0.f, 0.f);
            bvr = *(const float4*)(bptr + (size_t)(k0 + BK) * N);
        }
        #pragma unroll
        for (int kk = 0; kk < BK; kk++) {
            float4 a0 = *(const float4*)&As[buf][kk][ty * 4];
            float4 a1 = *(const float4*)&As[buf][kk][ty * 4 + 64];
            float4 b0 = *(const float4*)&Bs[buf][kk][tx * 4];
            float am[8] = {a0.x, a0.y, a0.z, a0.w, a1.x, a1.y, a1.z, a1.w};
            #pragma unroll
            for (int i = 0; i < 8; i++) {
                acc[i][0] += am[i] * b0.x;
                acc[i][1] += am[i] * b0.y;
                acc[i][2] += am[i] * b0.z;
                acc[i][3] += am[i] * b0.w;
            }
        }
        if (more) {
            int nb = buf ^ 1;
            #pragma unroll
            for (int i = 0; i < 2; i++) {
                As[nb][ak_[i] + 0][am_[i]] = avr[i].x;
                As[nb][ak_[i] + 1][am_[i]] = avr[i].y;
                As[nb][ak_[i] + 2][am_[i]] = avr[i].z;
                As[nb][ak_[i] + 3][am_[i]] = avr[i].w;
            }
            *(float4*)&Bs[nb][bk_][bn_] = bvr;
            __syncthreads();
            buf = nb;
        }
    }

    int n = n0 + tx * 4;
    float4 bb4 = *(const float4*)&bias[n];
    #pragma unroll
    for (int i = 0; i < 8; i++) {
        int m = m0 + ty * 4 + (i & 3) + ((i >= 4) ? 64 : 0);
        if (m >= Mtotal) continue;
        float4 v;
        v.x = acc[i][0] + bb4.x;
        v.y = acc[i][1] + bb4.y;
        v.z = acc[i][2] + bb4.z;
        v.w = acc[i][3] + bb4.w;
        if (act == 1) {
            v.x = 0.5f * v.x * (1.f + erff(v.x * 0.70710678118654752f));
            v.y = 0.5f * v.y * (1.f + erff(v.y * 0.70710678118654752f));
            v.z = 0.5f * v.z * (1.f + erff(v.z * 0.70710678118654752f));
            v.w = 0.5f * v.w * (1.f + erff(v.w * 0.70710678118654752f));
        }
        if (res) {
            float4 r = *(const float4*)&res[(size_t)m * N + n];
            v.x += r.x; v.y += r.y; v.z += r.z; v.w += r.w;
        }
        *(float4*)&C[(size_t)m * N + n] = v;
    }
}

// ---------------- embed ----------------
__global__ void k_embed(const float* __restrict__ cls, const float* __restrict__ pos,
                        const float* __restrict__ tok, float* __restrict__ X) {
    int t = blockIdx.x, b = blockIdx.y, d = threadIdx.x;
    const float4* src = (t == 0) ? (const float4*)cls
                                 : (const float4*)&tok[((size_t)(b * NPATCH + t - 1)) * Dm];
    float4 v = src[d];
    float4 p = ((const float4*)&pos[(size_t)t * Dm])[d];
    v.x += p.x; v.y += p.y; v.z += p.z; v.w += p.w;
    ((float4*)&X[((size_t)(b * TMAX + t)) * Dm])[d] = v;
}

// ---------------- LayerNorm ----------------
__global__ void k_ln(const float* __restrict__ X, const float* __restrict__ s,
                     const float* __restrict__ bb, float* __restrict__ O,
                     int useDyn, int ntokFixed) {
    int ntok = useDyn ? g_Ntok : ntokFixed;
    int t = blockIdx.x; if (t >= ntok) return;
    int b = blockIdx.y;
    const float* xr = X + ((size_t)(b * TMAX + t)) * Dm;
    __shared__ float red[128];
    int tid = threadIdx.x;
    float v0 = xr[tid], v1 = xr[tid + 128], v2 = xr[tid + 256];
    red[tid] = v0 + v1 + v2; __syncthreads();
    for (int st = 64; st > 0; st >>= 1) { if (tid < st) red[tid] += red[tid + st]; __syncthreads(); }
    float mean = red[0] / 384.f; __syncthreads();
    float d0 = v0 - mean, d1 = v1 - mean, d2 = v2 - mean;
    red[tid] = d0 * d0 + d1 * d1 + d2 * d2; __syncthreads();
    for (int st = 64; st > 0; st >>= 1) { if (tid < st) red[tid] += red[tid + st]; __syncthreads(); }
    float var = red[0] / 384.f;
    float inv = 1.f / sqrtf(var + 1e-5f);
    float* orow = O + ((size_t)(b * TMAX + t)) * Dm;
    orow[tid]       = d0 * inv * s[tid]       + bb[tid];
    orow[tid + 128] = d1 * inv * s[tid + 128] + bb[tid + 128];
    orow[tid + 256] = d2 * inv * s[tid + 256] + bb[tid + 256];
}

// ---------------- attention scores S = Q K^T * hd^-0.5 (64x64 tiles) ----------------
__global__ void __launch_bounds__(256) k_qk(const float* __restrict__ qkv) {
    int ntok = g_Ntok;
    int b = blockIdx.z / Hh, h = blockIdx.z % Hh;
    int q0 = blockIdx.y * 64, k0 = blockIdx.x * 64;
    if (q0 >= ntok || k0 >= ntok) return;
    __shared__ float Qs[64][65];
    __shared__ float Ks[64][65];
    int tid = threadIdx.x;
    #pragma unroll
    for (int i = 0; i < 4; i++) {
        int idx = tid + i * 256;
        int r = idx >> 4, d4 = (idx & 15) * 4;
        int tq = q0 + r, tk = k0 + r;
        float4 qv = (tq < ntok) ? *(const float4*)&qkv[((size_t)(b * TMAX + tq)) * 1152 + h * 64 + d4]
                                : make_float4(0.f, 0.f, 0.f, 0.f);
        float4 kv = (tk < ntok) ? *(const float4*)&qkv[((size_t)(b * TMAX + tk)) * 1152 + 384 + h * 64 + d4]
                                : make_float4(0.f, 0.f, 0.f, 0.f);
        Qs[r][d4] = qv.x; Qs[r][d4 + 1] = qv.y; Qs[r][d4 + 2] = qv.z; Qs[r][d4 + 3] = qv.w;
        Ks[r][d4] = kv.x; Ks[r][d4 + 1] = kv.y; Ks[r][d4 + 2] = kv.z; Ks[r][d4 + 3] = kv.w;
    }
    __syncthreads();
    int tx = tid & 15, ty = tid >> 4;
    float acc[4][4] = {};
    #pragma unroll 8
    for (int d = 0; d < 64; d++) {
        float a0 = Qs[ty * 4 + 0][d], a1 = Qs[ty * 4 + 1][d];
        float a2 = Qs[ty * 4 + 2][d], a3 = Qs[ty * 4 + 3][d];
        float b0 = Ks[tx * 4 + 0][d], b1 = Ks[tx * 4 + 1][d];
        float b2 = Ks[tx * 4 + 2][d], b3 = Ks[tx * 4 + 3][d];
        acc[0][0] += a0 * b0; acc[0][1] += a0 * b1; acc[0][2] += a0 * b2; acc[0][3] += a0 * b3;
        acc[1][0] += a1 * b0; acc[1][1] += a1 * b1; acc[1][2] += a1 * b2; acc[1][3] += a1 * b3;
        acc[2][0] += a2 * b0; acc[2][1] += a2 * b1; acc[2][2] += a2 * b2; acc[2][3] += a2 * b3;
        acc[3][0] += a3 * b0; acc[3][1] += a3 * b1; acc[3][2] += a3 * b2; acc[3][3] += a3 * b3;
    }
    float* Sb = g_S + ((size_t)(b * Hh + h)) * TMAX * SP;
    #pragma unroll
    for (int i = 0; i < 4; i++) {
        int q = q0 + ty * 4 + i;
        if (q >= ntok) continue;
        #pragma unroll
        for (int j = 0; j < 4; j++) {
            int k = k0 + tx * 4 + j;
            if (k < ntok) Sb[(size_t)q * SP + k] = acc[i][j] * 0.125f;
        }
    }
}

// ---------------- softmax rows (in place, pitched) + CLS entropy fused ----------------
__global__ void k_softmax() {
    int ntok = g_Ntok;
    int q = blockIdx.x; if (q >= ntok) return;
    int bh = blockIdx.y;
    float* row = g_S + ((size_t)bh * TMAX + q) * SP;
    __shared__ float red[256];
    int tid = threadIdx.x;
    float v[3]; float mx = -1e30f;
    #pragma unroll
    for (int i = 0; i < 3; i++) {
        int k = tid + 256 * i;
        v[i] = (k < ntok) ? row[k] : -1e30f;
        mx = fmaxf(mx, v[i]);
    }
    red[tid] = mx; __syncthreads();
    for (int st = 128; st > 0; st >>= 1) { if (tid < st) red[tid] = fmaxf(red[tid], red[tid + st]); __syncthreads(); }
    mx = red[0]; __syncthreads();
    float sm = 0.f;
    #pragma unroll
    for (int i = 0; i < 3; i++) {
        int k = tid + 256 * i;
        v[i] = (k < ntok) ? expf(v[i] - mx) : 0.f;
        sm += v[i];
    }
    red[tid] = sm; __syncthreads();
    for (int st = 128; st > 0; st >>= 1) { if (tid < st) red[tid] += red[tid + st]; __syncthreads(); }
    float inv = 1.f / red[0];
    #pragma unroll
    for (int i = 0; i < 3; i++) {
        int k = tid + 256 * i;
        if (k < ntok) row[k] = v[i] * inv;
    }
    if (q == 0) {
        __syncthreads();
        float e = 0.f;
        #pragma unroll
        for (int i = 0; i < 3; i++) {
            int k = tid + 256 * i;
            if (k < ntok) { float p = v[i] * inv; e += p * logf(p + 1e-6f); }
        }
        red[tid] = e; __syncthreads();
        for (int st = 128; st > 0; st >>= 1) { if (tid < st) red[tid] += red[tid + st]; __syncthreads(); }
        if (tid == 0) g_rho_bh[bh] = -red[0] / logf((float)ntok);
    }
}

// ---------------- out = attn @ V (64-row tiles, full d=64) ----------------
__global__ void __launch_bounds__(256) k_av(const float* __restrict__ qkv) {
    int ntok = g_Ntok;
    int q0 = blockIdx.x * 64; if (q0 >= ntok) return;
    int h = blockIdx.y, b = blockIdx.z;
    __shared__ float Ps[64][65];
    __shared__ float Vs[64][65];
    int tid = threadIdx.x, tx = tid & 15, ty = tid >> 4;
    float acc[4][4] = {};
    const float* Sb = g_S + ((size_t)(b * Hh + h)) * TMAX * SP;
    for (int k0 = 0; k0 < ntok; k0 += 64) {
        #pragma unroll
        for (int i = 0; i < 4; i++) {
            int idx = tid + i * 256;
            int r = idx >> 4, c4 = (idx & 15) * 4;
            int q = q0 + r;
            float4 pv = (q < ntok) ? *(const float4*)&Sb[(size_t)q * SP + k0 + c4]
                                   : make_float4(0.f, 0.f, 0.f, 0.f);
            Ps[r][c4] = pv.x; Ps[r][c4 + 1] = pv.y; Ps[r][c4 + 2] = pv.z; Ps[r][c4 + 3] = pv.w;
            int k = k0 + r;
            float4 vv = (k < ntok) ? *(const float4*)&qkv[((size_t)(b * TMAX + k)) * 1152 + 768 + h * 64 + c4]
                                   : make_float4(0.f, 0.f, 0.f, 0.f);
            Vs[r][c4] = vv.x; Vs[r][c4 + 1] = vv.y; Vs[r][c4 + 2] = vv.z; Vs[r][c4 + 3] = vv.w;
        }
        __syncthreads();
        #pragma unroll 8
        for (int kk = 0; kk < 64; kk++) {
            float a0 = Ps[ty * 4 + 0][kk], a1 = Ps[ty * 4 + 1][kk];
            float a2 = Ps[ty * 4 + 2][kk], a3 = Ps[ty * 4 + 3][kk];
            float b0 = Vs[kk][tx * 4 + 0], b1 = Vs[kk][tx * 4 + 1];
            float b2 = Vs[kk][tx * 4 + 2], b3 = Vs[kk][tx * 4 + 3];
            acc[0][0] += a0 * b0; acc[0][1] += a0 * b1; acc[0][2] += a0 * b2; acc[0][3] += a0 * b3;
            acc[1][0] += a1 * b0; acc[1][1] += a1 * b1; acc[1][2] += a1 * b2; acc[1][3] += a1 * b3;
            acc[2][0] += a2 * b0; acc[2][1] += a2 * b1; acc[2][2] += a2 * b2; acc[2][3] += a2 * b3;
            acc[3][0] += a3 * b0; acc[3][1] += a3 * b1; acc[3][2] += a3 * b2; acc[3][3] += a3 * b3;
        }
        __syncthreads();
    }
    #pragma unroll
    for (int i = 0; i < 4; i++) {
        int q = q0 + ty * 4 + i;
        if (q >= ntok) continue;
        #pragma unroll
        for (int j = 0; j < 4; j++)
            g_ao[((size_t)(b * TMAX + q)) * Dm + h * 64 + tx * 4 + j] = acc[i][j];
    }
}

// ---------------- stats: raw[b,k] = sum_h attn[b,h,0,k+1] * ||v[b,h,k+1]|| ----------------
__global__ void k_stats(const float* __restrict__ qkv) {
    int ntok = g_Ntok;
    int k = blockIdx.x * 192 + threadIdx.x;
    int b = blockIdx.y;
    if (k >= ntok - 1) return;
    const float4* vb = (const float4*)&qkv[((size_t)(b * TMAX + k + 1)) * 1152 + 768];
    const float* S0 = g_S + ((size_t)(b * Hh)) * TMAX * SP + (k + 1);
    float racc = 0.f;
    #pragma unroll
    for (int h = 0; h < Hh; h++) {
        float ss = 0.f;
        #pragma unroll
        for (int i = 0; i < 16; i++) {
            float4 v = vb[h * 16 + i];
            ss += v.x * v.x + v.y * v.y + v.z * v.z + v.w * v.w;
        }
        racc += S0[(size_t)h * TMAX * SP] * sqrtf(ss);
    }
    g_raw[b * NPATCH + k] = racc;
}

// ---------------- prune: mass + scores + controller + top-k + keep list ----------------
__global__ void k_prune() {
    __shared__ float sMass[Bc];
    __shared__ float wsum[Bc][18];
    __shared__ float sc[NPATCH];
    __shared__ unsigned char kp[NPATCH];
    __shared__ int sNn;
    int ntok = g_Ntok, Np = ntok - 1;
    int tid = threadIdx.x;
    int wid = tid >> 5, lid = tid & 31;

    #pragma unroll
    for (int b = 0; b < Bc; b++) {
        float v = (tid < Np) ? g_raw[b * NPATCH + tid] : 0.f;
        #pragma unroll
        for (int o = 16; o > 0; o >>= 1) v += __shfl_down_sync(0xffffffffu, v, o);
        if (lid == 0) wsum[b][wid] = v;
    }
    __syncthreads();
    if (tid < Bc) {
        float m = 0.f;
        for (int w = 0; w < 18; w++) m += wsum[tid][w];
        sMass[tid] = m;
    }
    __syncthreads();

    float score = 0.f;
    if (tid < Np) {
        #pragma unroll
        for (int b = 0; b < Bc; b++) score += g_raw[b * NPATCH + tid] / (sMass[b] + 1e-6f);
        score *= 0.125f;
    }
    sc[tid] = score;

    if (tid == 0) {
        int nn;
        if (Np > 16) {
            float mr = 0.f;
            for (int i = 0; i < Bc * Hh; i++) mr += g_rho_bh[i];
            mr /= 48.f;
            if (g_hasprev) {
                float md = 0.f;
                for (int b = 0; b < Bc; b++)
                    md += fabsf(sMass[b] - g_prevmass[b]) / (g_prevmass[b] + 1e-6f);
                md /= 8.f;
                float kr = 1.0f - 0.1f * (mr + md);
                kr = fminf(fmaxf(kr, 0.f), 1.f);
                nn = (int)((double)Np * (double)kr);
                if (nn < 16) nn = 16;
            } else {
                nn = Np;
            }
            for (int b = 0; b < Bc; b++) g_prevmass[b] = sMass[b];
            g_hasprev = 1;
        } else {
            nn = Np;
        }
        sNn = nn;
    }
    __syncthreads();
    int nn = sNn;

    int keep = 0;
    if (tid < Np) {
        float s = sc[tid];
        int rank = 0;
        for (int j = 0; j < Np; j++) {
            float o = sc[j];
            rank += (o > s) || (o == s && j < tid);
        }
        keep = (rank < nn);
    }
    kp[tid] = (unsigned char)keep;
    __syncthreads();
    if (keep) {
        int pos = 0;
        for (int j = 0; j < tid; j++) pos += kp[j];
        g_keep[pos + 1] = tid + 1;
    }
    if (tid == 0) { g_keep[0] = 0; g_Ntok = nn + 1; }
}

// ---------------- gather ----------------
__global__ void k_gather(const float* __restrict__ src, float* __restrict__ dst) {
    int ntok = g_Ntok;
    int t = blockIdx.x; if (t >= ntok) return;
    int b = blockIdx.y, d = threadIdx.x;
    int st = g_keep[t];
    ((float4*)&dst[((size_t)(b * TMAX + t)) * Dm])[d] =
        ((const float4*)&src[((size_t)(b * TMAX + st)) * Dm])[d];
}

// ---------------- classification head ----------------
__global__ void k_head(const float* __restrict__ xn, const float* __restrict__ W,
                       const float* __restrict__ bb, float* __restrict__ out) {
    int n = blockIdx.x * 128 + threadIdx.x;
    int b = blockIdx.y;
    if (n >= NCLSD) return;
    const float* xr = xn + (size_t)b * TMAX * Dm;
    float s = 0.f;
    for (int k = 0; k < Dm; k++) s += xr[k] * W[(size_t)k * NCLSD + n];
    out[b * NCLSD + n] = s + bb[n];
}

// ================================= host =================================
extern "C" void kernel_launch(void* const* d_in, const int* in_sizes, int n_in,
                              void* d_out, int out_size) {
    const float* x       = (const float*)d_in[0];
    const float* patch_w = (const float*)d_in[1];
    const float* patch_b = (const float*)d_in[2];
    const float* cls     = (const float*)d_in[3];
    const float* pos     = (const float*)d_in[4];
    const float* ln1_s   = (const float*)d_in[5];
    const float* ln1_b   = (const float*)d_in[6];
    const float* qkv_w   = (const float*)d_in[7];
    const float* qkv_b   = (const float*)d_in[8];
    const float* proj_w  = (const float*)d_in[9];
    const float* proj_b  = (const float*)d_in[10];
    const float* ln2_s   = (const float*)d_in[11];
    const float* ln2_b   = (const float*)d_in[12];
    const float* fc1_w   = (const float*)d_in[13];
    const float* fc1_b   = (const float*)d_in[14];
    const float* fc2_w   = (const float*)d_in[15];
    const float* fc2_b   = (const float*)d_in[16];
    const float* norm_s  = (const float*)d_in[17];
    const float* norm_b  = (const float*)d_in[18];
    const float* head_w  = (const float*)d_in[19];
    const float* head_b  = (const float*)d_in[20];
    float* out = (float*)d_out;

    float *pPatches, *pXA, *pXB, *pXn, *pQkv, *pAo, *pHid;
    cudaGetSymbolAddress((void**)&pPatches, g_patches);
    cudaGetSymbolAddress((void**)&pXA,  g_xA);
    cudaGetSymbolAddress((void**)&pXB,  g_xB);
    cudaGetSymbolAddress((void**)&pXn,  g_xn);
    cudaGetSymbolAddress((void**)&pQkv, g_qkv);
    cudaGetSymbolAddress((void**)&pAo,  g_ao);
    cudaGetSymbolAddress((void**)&pHid, g_hid);

    const int mT  = (MTOT + BM - 1) / BM;            // 37 flattened M-tiles
    const int mTp = (Bc * NPATCH + BM - 1) / BM;     // 36 for patch embed

    k_init<<<1, 1>>>();
    k_patchify<<<dim3(NPATCH, Bc), 256>>>(x);
    k_gemm<<<dim3(Dm / BN, mTp), 256>>>(
        pPatches, Bc * NPATCH, 768, patch_w, Dm, patch_b, (const float*)0, pAo, 0, 0);
    k_embed<<<dim3(TMAX, Bc), 96>>>(cls, pos, pAo, pXA);

    float* src = pXA;
    float* dst = pXB;
    const int aTiles = (TMAX + 63) / 64;     // 10
    for (int l = 0; l < Lc; l++) {
        k_ln<<<dim3(TMAX, Bc), 128>>>(src, ln1_s + l * Dm, ln1_b + l * Dm, pXn, 1, 0);
        k_gemm<<<dim3(1152 / BN, mT), 256>>>(
            pXn, MTOT, Dm, qkv_w + (size_t)l * Dm * 1152, 1152, qkv_b + l * 1152,
            (const float*)0, pQkv, 0, 1);
        k_qk<<<dim3(aTiles, aTiles, Bc * Hh), 256>>>(pQkv);
        k_softmax<<<dim3(TMAX, Bc * Hh), 256>>>();
        k_av<<<dim3(aTiles, Hh, Bc), 256>>>(pQkv);
        k_stats<<<dim3(3, Bc), 192>>>(pQkv);
        k_gemm<<<dim3(Dm / BN, mT), 256>>>(
            pAo, MTOT, Dm, proj_w + (size_t)l * Dm * Dm, Dm, proj_b + l * Dm,
            src, src, 0, 1);
        k_ln<<<dim3(TMAX, Bc), 128>>>(src, ln2_s + l * Dm, ln2_b + l * Dm, pXn, 1, 0);
        k_gemm<<<dim3(MLPD / BN, mT), 256>>>(
            pXn, MTOT, Dm, fc1_w + (size_t)l * Dm * MLPD, MLPD, fc1_b + l * MLPD,
            (const float*)0, pHid, 1, 1);
        k_gemm<<<dim3(Dm / BN, mT), 256>>>(
            pHid, MTOT, MLPD, fc2_w + (size_t)l * MLPD * Dm, Dm, fc2_b + l * Dm,
            src, src, 0, 1);
        k_prune<<<1, NPATCH>>>();
        k_gather<<<dim3(TMAX, Bc), 96>>>(src, dst);
        float* tmp = src; src = dst; dst = tmp;
    }

    k_ln<<<dim3(1, Bc), 128>>>(src, norm_s, norm_b, pXn, 0, 1);
    k_head<<<dim3((NCLSD + 127) / 128, Bc), 128>>>(pXn, head_w, head_b, out);
}

// round 6
// speedup vs baseline: 1.4171x; 1.0681x over previous
#include <cuda_runtime.h>
#include <math.h>

#define Bc 8
#define Dm 384
#define Hh 6
#define HD 64
#define Lc 12
#define MLPD 1536
#define NCLSD 1000
#define TMAX 577
#define NPATCH 576
#define GG 24
#define MTOT (Bc * TMAX)   // 4616 flattened rows

#define BM 128
#define BN 64
#define BK 16
#define APAD 132
#define BPAD 68

// k_attn dynamic smem: Qs/Ks/Vs/Ps (64x65 each) + rm/rl/rf (64 each)
#define TS 65
#define ATTN_SMEM ((4 * 64 * TS + 3 * 64) * 4)

// ---------------- scratch (device globals; no allocation allowed) ----------------
__device__ float g_patches[Bc * NPATCH * 768];
__device__ float g_xA[Bc * TMAX * Dm];
__device__ float g_xB[Bc * TMAX * Dm];
__device__ float g_xn[Bc * TMAX * Dm];
__device__ float g_qkv[Bc * TMAX * 3 * Dm];
__device__ float g_ao[Bc * TMAX * Dm];
__device__ float g_hid[Bc * TMAX * MLPD];
__device__ float g_clsS[Bc * Hh * TMAX];      // raw scaled CLS scores
__device__ float g_clsattn[Bc * Hh * TMAX];   // softmaxed CLS attention row
__device__ float g_rho_bh[Bc * Hh];
__device__ float g_raw[Bc * NPATCH];
__device__ float g_prevmass[Bc];
__device__ int   g_keep[TMAX];
__device__ int   g_Ntok;
__device__ int   g_hasprev;

// ---------------- init ----------------
__global__ void k_init() { g_Ntok = TMAX; g_hasprev = 0; }

// ---------------- patchify ----------------
__global__ void k_patchify(const float* __restrict__ x) {
    int p = blockIdx.x, b = blockIdx.y;
    int gy = p / GG, gx = p % GG;
    for (int f = threadIdx.x; f < 768; f += blockDim.x) {
        int c = f >> 8, r = (f >> 4) & 15, cc = f & 15;
        g_patches[((size_t)(b * NPATCH + p)) * 768 + f] =
            x[(((size_t)(b * 3 + c)) * 384 + gy * 16 + r) * 384 + gx * 16 + cc];
    }
}

// ---------------- 128x64x16 fp32 GEMM, double-buffered, batch-flattened M ----------------
__global__ void __launch_bounds__(256) k_gemm(
    const float* __restrict__ A, int Mtotal, int K,
    const float* __restrict__ W, int N,
    const float* __restrict__ bias,
    const float* __restrict__ res,
    float* __restrict__ C,
    int act, int useDyn)
{
    int m0 = blockIdx.y * BM;
    int n0 = blockIdx.x * BN;
    if (useDyn) {
        int ntok = g_Ntok;
        int tstart = m0 % TMAX;
        if (tstart >= ntok && tstart + BM - 1 < TMAX) return;
    }
    __shared__ __align__(16) float As[2][BK][APAD];
    __shared__ __align__(16) float Bs[2][BK][BPAD];

    int tid = threadIdx.x;
    int tx = tid & 15, ty = tid >> 4;

    int am_[2], ak_[2];
    bool aval[2];
    const float* aptr[2];
    #pragma unroll
    for (int i = 0; i < 2; i++) {
        int idx = tid + i * 256;
        am_[i] = idx >> 2;
        ak_[i] = (idx & 3) * 4;
        int m = m0 + am_[i];
        aval[i] = (m < Mtotal);
        aptr[i] = A + (size_t)(aval[i] ? m : 0) * K + ak_[i];
    }
    int bk_ = tid >> 4;
    int bn_ = (tid & 15) * 4;
    const float* bptr = W + (size_t)bk_ * N + n0 + bn_;

    float4 avr[2], bvr;
    #pragma unroll
    for (int i = 0; i < 2; i++)
        avr[i] = aval[i] ? *(const float4*)(aptr[i]) : make_float4(0.f, 0.f, 0.f, 0.f);
    bvr = *(const float4*)(bptr);

    #pragma unroll
    for (int i = 0; i < 2; i++) {
        As[0][ak_[i] + 0][am_[i]] = avr[i].x;
        As[0][ak_[i] + 1][am_[i]] = avr[i].y;
        As[0][ak_[i] + 2][am_[i]] = avr[i].z;
        As[0][ak_[i] + 3][am_[i]] = avr[i].w;
    }
    *(float4*)&Bs[0][bk_][bn_] = bvr;
    __syncthreads();

    float acc[8][4] = {};
    int buf = 0;
    for (int k0 = 0; k0 < K; k0 += BK) {
        bool more = (k0 + BK < K);
        if (more) {
            #pragma unroll
            for (int i = 0; i < 2; i++)
                avr[i] = aval[i] ? *(const float4*)(aptr[i] + k0 + BK) : make_float4(0.f, 0.f, 0.f, 0.f);
            bvr = *(const float4*)(bptr + (size_t)(k0 + BK) * N);
        }
        #pragma unroll
        for (int kk = 0; kk < BK; kk++) {
            float4 a0 = *(const float4*)&As[buf][kk][ty * 4];
            float4 a1 = *(const float4*)&As[buf][kk][ty * 4 + 64];
            float4 b0 = *(const float4*)&Bs[buf][kk][tx * 4];
            float am[8] = {a0.x, a0.y, a0.z, a0.w, a1.x, a1.y, a1.z, a1.w};
            #pragma unroll
            for (int i = 0; i < 8; i++) {
                acc[i][0] += am[i] * b0.x;
                acc[i][1] += am[i] * b0.y;
                acc[i][2] += am[i] * b0.z;
                acc[i][3] += am[i] * b0.w;
            }
        }
        if (more) {
            int nb = buf ^ 1;
            #pragma unroll
            for (int i = 0; i < 2; i++) {
                As[nb][ak_[i] + 0][am_[i]] = avr[i].x;
                As[nb][ak_[i] + 1][am_[i]] = avr[i].y;
                As[nb][ak_[i] + 2][am_[i]] = avr[i].z;
                As[nb][ak_[i] + 3][am_[i]] = avr[i].w;
            }
            *(float4*)&Bs[nb][bk_][bn_] = bvr;
            __syncthreads();
            buf = nb;
        }
    }

    int n = n0 + tx * 4;
    float4 bb4 = *(const float4*)&bias[n];
    #pragma unroll
    for (int i = 0; i < 8; i++) {
        int m = m0 + ty * 4 + (i & 3) + ((i >= 4) ? 64 : 0);
        if (m >= Mtotal) continue;
        float4 v;
        v.x = acc[i][0] + bb4.x;
        v.y = acc[i][1] + bb4.y;
        v.z = acc[i][2] + bb4.z;
        v.w = acc[i][3] + bb4.w;
        if (act == 1) {
            v.x = 0.5f * v.x * (1.f + erff(v.x * 0.70710678118654752f));
            v.y = 0.5f * v.y * (1.f + erff(v.y * 0.70710678118654752f));
            v.z = 0.5f * v.z * (1.f + erff(v.z * 0.70710678118654752f));
            v.w = 0.5f * v.w * (1.f + erff(v.w * 0.70710678118654752f));
        }
        if (res) {
            float4 r = *(const float4*)&res[(size_t)m * N + n];
            v.x += r.x; v.y += r.y; v.z += r.z; v.w += r.w;
        }
        *(float4*)&C[(size_t)m * N + n] = v;
    }
}

// ---------------- embed ----------------
__global__ void k_embed(const float* __restrict__ cls, const float* __restrict__ pos,
                        const float* __restrict__ tok, float* __restrict__ X) {
    int t = blockIdx.x, b = blockIdx.y, d = threadIdx.x;
    const float4* src = (t == 0) ? (const float4*)cls
                                 : (const float4*)&tok[((size_t)(b * NPATCH + t - 1)) * Dm];
    float4 v = src[d];
    float4 p = ((const float4*)&pos[(size_t)t * Dm])[d];
    v.x += p.x; v.y += p.y; v.z += p.z; v.w += p.w;
    ((float4*)&X[((size_t)(b * TMAX + t)) * Dm])[d] = v;
}

// ---------------- LayerNorm ----------------
__global__ void k_ln(const float* __restrict__ X, const float* __restrict__ s,
                     const float* __restrict__ bb, float* __restrict__ O,
                     int useDyn, int ntokFixed) {
    int ntok = useDyn ? g_Ntok : ntokFixed;
    int t = blockIdx.x; if (t >= ntok) return;
    int b = blockIdx.y;
    const float* xr = X + ((size_t)(b * TMAX + t)) * Dm;
    __shared__ float red[128];
    int tid = threadIdx.x;
    float v0 = xr[tid], v1 = xr[tid + 128], v2 = xr[tid + 256];
    red[tid] = v0 + v1 + v2; __syncthreads();
    for (int st = 64; st > 0; st >>= 1) { if (tid < st) red[tid] += red[tid + st]; __syncthreads(); }
    float mean = red[0] / 384.f; __syncthreads();
    float d0 = v0 - mean, d1 = v1 - mean, d2 = v2 - mean;
    red[tid] = d0 * d0 + d1 * d1 + d2 * d2; __syncthreads();
    for (int st = 64; st > 0; st >>= 1) { if (tid < st) red[tid] += red[tid + st]; __syncthreads(); }
    float var = red[0] / 384.f;
    float inv = 1.f / sqrtf(var + 1e-5f);
    float* orow = O + ((size_t)(b * TMAX + t)) * Dm;
    orow[tid]       = d0 * inv * s[tid]       + bb[tid];
    orow[tid + 128] = d1 * inv * s[tid + 128] + bb[tid + 128];
    orow[tid + 256] = d2 * inv * s[tid + 256] + bb[tid + 256];
}

// ---------------- fused attention: S=QK^T, online softmax, O=P@V ----------------
// grid (qTiles, Hh, Bc), 256 threads, dynamic smem ATTN_SMEM
__global__ void __launch_bounds__(256) k_attn(const float* __restrict__ qkv) {
    int ntok = g_Ntok;
    int q0 = blockIdx.x * 64; if (q0 >= ntok) return;
    int h = blockIdx.y, b = blockIdx.z;
    extern __shared__ float smbuf[];
    float (*Qs)[TS] = (float(*)[TS])(smbuf);
    float (*Ks)[TS] = (float(*)[TS])(smbuf + 64 * TS);
    float (*Vs)[TS] = (float(*)[TS])(smbuf + 2 * 64 * TS);
    float (*Ps)[TS] = (float(*)[TS])(smbuf + 3 * 64 * TS);
    float* rm = smbuf + 4 * 64 * TS;
    float* rl = rm + 64;
    float* rf = rl + 64;

    int tid = threadIdx.x, tx = tid & 15, ty = tid >> 4;

    // load Q tile once
    #pragma unroll
    for (int i = 0; i < 4; i++) {
        int idx = tid + i * 256;
        int r = idx >> 4, d4 = (idx & 15) * 4;
        int tq = q0 + r;
        float4 qv = (tq < ntok) ? *(const float4*)&qkv[((size_t)(b * TMAX + tq)) * 1152 + h * 64 + d4]
                                : make_float4(0.f, 0.f, 0.f, 0.f);
        Qs[r][d4] = qv.x; Qs[r][d4 + 1] = qv.y; Qs[r][d4 + 2] = qv.z; Qs[r][d4 + 3] = qv.w;
    }
    if (tid < 64) { rm[tid] = -1e30f; rl[tid] = 0.f; }
    __syncthreads();

    float oacc[4][4] = {};
    int row = tid >> 2, part = tid & 3;   // row-pass mapping

    for (int k0 = 0; k0 < ntok; k0 += 64) {
        // load K and V tiles
        #pragma unroll
        for (int i = 0; i < 4; i++) {
            int idx = tid + i * 256;
            int r = idx >> 4, d4 = (idx & 15) * 4;
            int tk = k0 + r;
            float4 kv = (tk < ntok) ? *(const float4*)&qkv[((size_t)(b * TMAX + tk)) * 1152 + 384 + h * 64 + d4]
                                    : make_float4(0.f, 0.f, 0.f, 0.f);
            float4 vv = (tk < ntok) ? *(const float4*)&qkv[((size_t)(b * TMAX + tk)) * 1152 + 768 + h * 64 + d4]
                                    : make_float4(0.f, 0.f, 0.f, 0.f);
            Ks[r][d4] = kv.x; Ks[r][d4 + 1] = kv.y; Ks[r][d4 + 2] = kv.z; Ks[r][d4 + 3] = kv.w;
            Vs[r][d4] = vv.x; Vs[r][d4 + 1] = vv.y; Vs[r][d4 + 2] = vv.z; Vs[r][d4 + 3] = vv.w;
        }
        __syncthreads();

        // S tile = Q K^T (same FMA order as the old k_qk)
        float acc[4][4] = {};
        #pragma unroll 8
        for (int d = 0; d < 64; d++) {
            float a0 = Qs[ty * 4 + 0][d], a1 = Qs[ty * 4 + 1][d];
            float a2 = Qs[ty * 4 + 2][d], a3 = Qs[ty * 4 + 3][d];
            float b0 = Ks[tx * 4 + 0][d], b1 = Ks[tx * 4 + 1][d];
            float b2 = Ks[tx * 4 + 2][d], b3 = Ks[tx * 4 + 3][d];
            acc[0][0] += a0 * b0; acc[0][1] += a0 * b1; acc[0][2] += a0 * b2; acc[0][3] += a0 * b3;
            acc[1][0] += a1 * b0; acc[1][1] += a1 * b1; acc[1][2] += a1 * b2; acc[1][3] += a1 * b3;
            acc[2][0] += a2 * b0; acc[2][1] += a2 * b1; acc[2][2] += a2 * b2; acc[2][3] += a2 * b3;
            acc[3][0] += a3 * b0; acc[3][1] += a3 * b1; acc[3][2] += a3 * b2; acc[3][3] += a3 * b3;
        }
        // store scaled scores (+ -inf padding), raw CLS row to global
        #pragma unroll
        for (int i = 0; i < 4; i++) {
            #pragma unroll
            for (int j = 0; j < 4; j++) {
                int kcol = k0 + tx * 4 + j;
                Ps[ty * 4 + i][tx * 4 + j] = (kcol < ntok) ? acc[i][j] * 0.125f : -1e30f;
            }
        }
        if (q0 == 0 && ty == 0) {
            #pragma unroll
            for (int j = 0; j < 4; j++) {
                int kcol = k0 + tx * 4 + j;
                if (kcol < ntok)
                    g_clsS[((size_t)(b * Hh + h)) * TMAX + kcol] = acc[0][j] * 0.125f;
            }
        }
        __syncthreads();

        // online softmax row pass: 4 threads per row, 16 cols each
        float tm = -1e30f;
        #pragma unroll
        for (int c = 0; c < 16; c++) tm = fmaxf(tm, Ps[row][part * 16 + c]);
        tm = fmaxf(tm, __shfl_xor_sync(0xffffffffu, tm, 1));
        tm = fmaxf(tm, __shfl_xor_sync(0xffffffffu, tm, 2));
        float mold = rm[row];
        float mnew = fmaxf(mold, tm);
        float psum = 0.f;
        #pragma unroll
        for (int c = 0; c < 16; c++) {
            float p = expf(Ps[row][part * 16 + c] - mnew);
            Ps[row][part * 16 + c] = p;
            psum += p;
        }
        psum += __shfl_xor_sync(0xffffffffu, psum, 1);
        psum += __shfl_xor_sync(0xffffffffu, psum, 2);
        if (part == 0) {
            float f = expf(mold - mnew);   // mold=-1e30 -> 0
            rf[row] = f;
            rl[row] = rl[row] * f + psum;
            rm[row] = mnew;
        }
        __syncthreads();

        // rescale accumulators, then O += P @ V
        #pragma unroll
        for (int i = 0; i < 4; i++) {
            float f = rf[ty * 4 + i];
            oacc[i][0] *= f; oacc[i][1] *= f; oacc[i][2] *= f; oacc[i][3] *= f;
        }
        #pragma unroll 8
        for (int kk = 0; kk < 64; kk++) {
            float a0 = Ps[ty * 4 + 0][kk], a1 = Ps[ty * 4 + 1][kk];
            float a2 = Ps[ty * 4 + 2][kk], a3 = Ps[ty * 4 + 3][kk];
            float b0 = Vs[kk][tx * 4 + 0], b1 = Vs[kk][tx * 4 + 1];
            float b2 = Vs[kk][tx * 4 + 2], b3 = Vs[kk][tx * 4 + 3];
            oacc[0][0] += a0 * b0; oacc[0][1] += a0 * b1; oacc[0][2] += a0 * b2; oacc[0][3] += a0 * b3;
            oacc[1][0] += a1 * b0; oacc[1][1] += a1 * b1; oacc[1][2] += a1 * b2; oacc[1][3] += a1 * b3;
            oacc[2][0] += a2 * b0; oacc[2][1] += a2 * b1; oacc[2][2] += a2 * b2; oacc[2][3] += a2 * b3;
            oacc[3][0] += a3 * b0; oacc[3][1] += a3 * b1; oacc[3][2] += a3 * b2; oacc[3][3] += a3 * b3;
        }
        __syncthreads();
    }

    #pragma unroll
    for (int i = 0; i < 4; i++) {
        int q = q0 + ty * 4 + i;
        if (q >= ntok) continue;
        float inv = 1.f / rl[ty * 4 + i];
        float* orow = &g_ao[((size_t)(b * TMAX + q)) * Dm + h * 64 + tx * 4];
        orow[0] = oacc[i][0] * inv;
        orow[1] = oacc[i][1] * inv;
        orow[2] = oacc[i][2] * inv;
        orow[3] = oacc[i][3] * inv;
    }
}

// ---------------- CLS softmax + entropy (exact, same reductions as before) ----------------
__global__ void k_cls() {
    int ntok = g_Ntok;
    int bh = blockIdx.x;
    const float* rowS = g_clsS + (size_t)bh * TMAX;
    float* rowP = g_clsattn + (size_t)bh * TMAX;
    __shared__ float red[256];
    int tid = threadIdx.x;
    float v[3]; float mx = -1e30f;
    #pragma unroll
    for (int i = 0; i < 3; i++) {
        int k = tid + 256 * i;
        v[i] = (k < ntok) ? rowS[k] : -1e30f;
        mx = fmaxf(mx, v[i]);
    }
    red[tid] = mx; __syncthreads();
    for (int st = 128; st > 0; st >>= 1) { if (tid < st) red[tid] = fmaxf(red[tid], red[tid + st]); __syncthreads(); }
    mx = red[0]; __syncthreads();
    float sm = 0.f;
    #pragma unroll
    for (int i = 0; i < 3; i++) {
        int k = tid + 256 * i;
        v[i] = (k < ntok) ? expf(v[i] - mx) : 0.f;
        sm += v[i];
    }
    red[tid] = sm; __syncthreads();
    for (int st = 128; st > 0; st >>= 1) { if (tid < st) red[tid] += red[tid + st]; __syncthreads(); }
    float inv = 1.f / red[0];
    float e = 0.f;
    #pragma unroll
    for (int i = 0; i < 3; i++) {
        int k = tid + 256 * i;
        if (k < ntok) {
            float p = v[i] * inv;
            rowP[k] = p;
            e += p * logf(p + 1e-6f);
        }
    }
    __syncthreads();
    red[tid] = e; __syncthreads();
    for (int st = 128; st > 0; st >>= 1) { if (tid < st) red[tid] += red[tid + st]; __syncthreads(); }
    if (tid == 0) g_rho_bh[bh] = -red[0] / logf((float)ntok);
}

// ---------------- stats: raw[b,k] = sum_h attn[b,h,0,k+1] * ||v[b,h,k+1]|| ----------------
__global__ void k_stats(const float* __restrict__ qkv) {
    int ntok = g_Ntok;
    int k = blockIdx.x * 192 + threadIdx.x;
    int b = blockIdx.y;
    if (k >= ntok - 1) return;
    const float4* vb = (const float4*)&qkv[((size_t)(b * TMAX + k + 1)) * 1152 + 768];
    const float* P0 = g_clsattn + (size_t)(b * Hh) * TMAX + (k + 1);
    float racc = 0.f;
    #pragma unroll
    for (int h = 0; h < Hh; h++) {
        float ss = 0.f;
        #pragma unroll
        for (int i = 0; i < 16; i++) {
            float4 v = vb[h * 16 + i];
            ss += v.x * v.x + v.y * v.y + v.z * v.z + v.w * v.w;
        }
        racc += P0[(size_t)h * TMAX] * sqrtf(ss);
    }
    g_raw[b * NPATCH + k] = racc;
}

// ---------------- prune ----------------
__global__ void k_prune() {
    __shared__ float sMass[Bc];
    __shared__ float wsum[Bc][18];
    __shared__ float sc[NPATCH];
    __shared__ unsigned char kp[NPATCH];
    __shared__ int sNn;
    int ntok = g_Ntok, Np = ntok - 1;
    int tid = threadIdx.x;
    int wid = tid >> 5, lid = tid & 31;

    #pragma unroll
    for (int b = 0; b < Bc; b++) {
        float v = (tid < Np) ? g_raw[b * NPATCH + tid] : 0.f;
        #pragma unroll
        for (int o = 16; o > 0; o >>= 1) v += __shfl_down_sync(0xffffffffu, v, o);
        if (lid == 0) wsum[b][wid] = v;
    }
    __syncthreads();
    if (tid < Bc) {
        float m = 0.f;
        for (int w = 0; w < 18; w++) m += wsum[tid][w];
        sMass[tid] = m;
    }
    __syncthreads();

    float score = 0.f;
    if (tid < Np) {
        #pragma unroll
        for (int b = 0; b < Bc; b++) score += g_raw[b * NPATCH + tid] / (sMass[b] + 1e-6f);
        score *= 0.125f;
    }
    sc[tid] = score;

    if (tid == 0) {
        int nn;
        if (Np > 16) {
            float mr = 0.f;
            for (int i = 0; i < Bc * Hh; i++) mr += g_rho_bh[i];
            mr /= 48.f;
            if (g_hasprev) {
                float md = 0.f;
                for (int b = 0; b < Bc; b++)
                    md += fabsf(sMass[b] - g_prevmass[b]) / (g_prevmass[b] + 1e-6f);
                md /= 8.f;
                float kr = 1.0f - 0.1f * (mr + md);
                kr = fminf(fmaxf(kr, 0.f), 1.f);
                nn = (int)((double)Np * (double)kr);
                if (nn < 16) nn = 16;
            } else {
                nn = Np;
            }
            for (int b = 0; b < Bc; b++) g_prevmass[b] = sMass[b];
            g_hasprev = 1;
        } else {
            nn = Np;
        }
        sNn = nn;
    }
    __syncthreads();
    int nn = sNn;

    int keep = 0;
    if (tid < Np) {
        float s = sc[tid];
        int rank = 0;
        for (int j = 0; j < Np; j++) {
            float o = sc[j];
            rank += (o > s) || (o == s && j < tid);
        }
        keep = (rank < nn);
    }
    kp[tid] = (unsigned char)keep;
    __syncthreads();
    if (keep) {
        int pos = 0;
        for (int j = 0; j < tid; j++) pos += kp[j];
        g_keep[pos + 1] = tid + 1;
    }
    if (tid == 0) { g_keep[0] = 0; g_Ntok = nn + 1; }
}

// ---------------- gather ----------------
__global__ void k_gather(const float* __restrict__ src, float* __restrict__ dst) {
    int ntok = g_Ntok;
    int t = blockIdx.x; if (t >= ntok) return;
    int b = blockIdx.y, d = threadIdx.x;
    int st = g_keep[t];
    ((float4*)&dst[((size_t)(b * TMAX + t)) * Dm])[d] =
        ((const float4*)&src[((size_t)(b * TMAX + st)) * Dm])[d];
}

// ---------------- classification head ----------------
__global__ void k_head(const float* __restrict__ xn, const float* __restrict__ W,
                       const float* __restrict__ bb, float* __restrict__ out) {
    int n = blockIdx.x * 128 + threadIdx.x;
    int b = blockIdx.y;
    if (n >= NCLSD) return;
    const float* xr = xn + (size_t)b * TMAX * Dm;
    float s = 0.f;
    for (int k = 0; k < Dm; k++) s += xr[k] * W[(size_t)k * NCLSD + n];
    out[b * NCLSD + n] = s + bb[n];
}

// ================================= host =================================
extern "C" void kernel_launch(void* const* d_in, const int* in_sizes, int n_in,
                              void* d_out, int out_size) {
    const float* x       = (const float*)d_in[0];
    const float* patch_w = (const float*)d_in[1];
    const float* patch_b = (const float*)d_in[2];
    const float* cls     = (const float*)d_in[3];
    const float* pos     = (const float*)d_in[4];
    const float* ln1_s   = (const float*)d_in[5];
    const float* ln1_b   = (const float*)d_in[6];
    const float* qkv_w   = (const float*)d_in[7];
    const float* qkv_b   = (const float*)d_in[8];
    const float* proj_w  = (const float*)d_in[9];
    const float* proj_b  = (const float*)d_in[10];
    const float* ln2_s   = (const float*)d_in[11];
    const float* ln2_b   = (const float*)d_in[12];
    const float* fc1_w   = (const float*)d_in[13];
    const float* fc1_b   = (const float*)d_in[14];
    const float* fc2_w   = (const float*)d_in[15];
    const float* fc2_b   = (const float*)d_in[16];
    const float* norm_s  = (const float*)d_in[17];
    const float* norm_b  = (const float*)d_in[18];
    const float* head_w  = (const float*)d_in[19];
    const float* head_b  = (const float*)d_in[20];
    float* out = (float*)d_out;

    float *pPatches, *pXA, *pXB, *pXn, *pQkv, *pAo, *pHid;
    cudaGetSymbolAddress((void**)&pPatches, g_patches);
    cudaGetSymbolAddress((void**)&pXA,  g_xA);
    cudaGetSymbolAddress((void**)&pXB,  g_xB);
    cudaGetSymbolAddress((void**)&pXn,  g_xn);
    cudaGetSymbolAddress((void**)&pQkv, g_qkv);
    cudaGetSymbolAddress((void**)&pAo,  g_ao);
    cudaGetSymbolAddress((void**)&pHid, g_hid);

    cudaFuncSetAttribute(k_attn, cudaFuncAttributeMaxDynamicSharedMemorySize, ATTN_SMEM);

    const int mT  = (MTOT + BM - 1) / BM;            // 37 flattened M-tiles
    const int mTp = (Bc * NPATCH + BM - 1) / BM;     // 36 for patch embed

    k_init<<<1, 1>>>();
    k_patchify<<<dim3(NPATCH, Bc), 256>>>(x);
    k_gemm<<<dim3(Dm / BN, mTp), 256>>>(
        pPatches, Bc * NPATCH, 768, patch_w, Dm, patch_b, (const float*)0, pAo, 0, 0);
    k_embed<<<dim3(TMAX, Bc), 96>>>(cls, pos, pAo, pXA);

    float* src = pXA;
    float* dst = pXB;
    const int aTiles = (TMAX + 63) / 64;     // 10
    for (int l = 0; l < Lc; l++) {
        k_ln<<<dim3(TMAX, Bc), 128>>>(src, ln1_s + l * Dm, ln1_b + l * Dm, pXn, 1, 0);
        k_gemm<<<dim3(1152 / BN, mT), 256>>>(
            pXn, MTOT, Dm, qkv_w + (size_t)l * Dm * 1152, 1152, qkv_b + l * 1152,
            (const float*)0, pQkv, 0, 1);
        k_attn<<<dim3(aTiles, Hh, Bc), 256, ATTN_SMEM>>>(pQkv);
        k_cls<<<Bc * Hh, 256>>>();
        k_stats<<<dim3(3, Bc), 192>>>(pQkv);
        k_gemm<<<dim3(Dm / BN, mT), 256>>>(
            pAo, MTOT, Dm, proj_w + (size_t)l * Dm * Dm, Dm, proj_b + l * Dm,
            src, src, 0, 1);
        k_ln<<<dim3(TMAX, Bc), 128>>>(src, ln2_s + l * Dm, ln2_b + l * Dm, pXn, 1, 0);
        k_gemm<<<dim3(MLPD / BN, mT), 256>>>(
            pXn, MTOT, Dm, fc1_w + (size_t)l * Dm * MLPD, MLPD, fc1_b + l * MLPD,
            (const float*)0, pHid, 1, 1);
        k_gemm<<<dim3(Dm / BN, mT), 256>>>(
            pHid, MTOT, MLPD, fc2_w + (size_t)l * MLPD * Dm, Dm, fc2_b + l * Dm,
            src, src, 0, 1);
        k_prune<<<1, NPATCH>>>();
        k_gather<<<dim3(TMAX, Bc), 96>>>(src, dst);
        float* tmp = src; src = dst; dst = tmp;
    }

    k_ln<<<dim3(1, Bc), 128>>>(src, norm_s, norm_b, pXn, 0, 1);
    k_head<<<dim3((NCLSD + 127) / 128, Bc), 128>>>(pXn, head_w, head_b, out);
}